// round 13
// baseline (speedup 1.0000x reference)
#include <cuda_runtime.h>
#include <cuda_bf16.h>
#include <cstdint>

#define NTAGS 128
#define BATCH 256
#define SLEN  512

// ---- packed f32x2 helpers (sm_103a) ----
__device__ __forceinline__ unsigned long long pk2(float x, float y) {
    unsigned long long r;
    asm("mov.b64 %0,{%1,%2};" : "=l"(r) : "f"(x), "f"(y));
    return r;
}
__device__ __forceinline__ void upk2(unsigned long long v, float& x, float& y) {
    asm("mov.b64 {%0,%1},%2;" : "=f"(x), "=f"(y) : "l"(v));
}
__device__ __forceinline__ unsigned long long ffma2(unsigned long long a,
                                                    unsigned long long b,
                                                    unsigned long long c) {
    unsigned long long d;
    asm("fma.rn.f32x2 %0,%1,%2,%3;" : "=l"(d) : "l"(a), "l"(b), "l"(c));
    return d;
}
__device__ __forceinline__ unsigned long long add2(unsigned long long a,
                                                   unsigned long long b) {
    unsigned long long d;
    asm("add.rn.f32x2 %0,%1,%2;" : "=l"(d) : "l"(a), "l"(b));
    return d;
}

// matvec: u_j = sum_i w_i * eT[i][j], w in smem (broadcast LDS.128), eT col in regs
__device__ __forceinline__ float matvec128(const float* __restrict__ pb,
                                           const unsigned long long* __restrict__ col) {
    const ulonglong2* pq = (const ulonglong2*)pb;
    unsigned long long a0 = 0ull, a1 = 0ull, a2 = 0ull, a3 = 0ull;
    unsigned long long a4 = 0ull, a5 = 0ull, a6 = 0ull, a7 = 0ull;
#pragma unroll
    for (int k = 0; k < 32; k += 4) {
        ulonglong2 q0 = pq[k];
        ulonglong2 q1 = pq[k + 1];
        ulonglong2 q2 = pq[k + 2];
        ulonglong2 q3 = pq[k + 3];
        a0 = ffma2(q0.x, col[2 * k],     a0);
        a1 = ffma2(q0.y, col[2 * k + 1], a1);
        a2 = ffma2(q1.x, col[2 * k + 2], a2);
        a3 = ffma2(q1.y, col[2 * k + 3], a3);
        a4 = ffma2(q2.x, col[2 * k + 4], a4);
        a5 = ffma2(q2.y, col[2 * k + 5], a5);
        a6 = ffma2(q3.x, col[2 * k + 6], a6);
        a7 = ffma2(q3.y, col[2 * k + 7], a7);
    }
    unsigned long long st = add2(add2(add2(a0, a1), add2(a2, a3)),
                                 add2(add2(a4, a5), add2(a6, a7)));
    float sx, sy;
    upk2(st, sx, sy);
    return sx + sy;
}

__global__ void crf_zero_out(float* out) { out[0] = 0.0f; }

__global__ void __launch_bounds__(NTAGS, 1)
crf_forward_kernel(const float* __restrict__ emissions,      // [B,S,NTAGS]
                   const void* __restrict__ tags_raw,        // [B,S] int32 OR int64
                   const unsigned char* __restrict__ mask,   // [B,S]
                   const float* __restrict__ transitions,    // [NTAGS,NTAGS]
                   float* __restrict__ out)                  // [1]
{
    const int b0   = 2 * blockIdx.x;      // this CTA runs two batch chains
    const int b1   = b0 + 1;
    const int j    = threadIdx.x;         // tag owned by this thread
    const int lane = j & 31;
    const int wid  = j >> 5;

    __shared__ __align__(16) float pbuf[2][2][NTAGS];  // [chain][buf][tag]
    __shared__ float u0s[2][2];                        // [chain][buf]
    __shared__ float red[12];                          // epilogue scratch

    // -------- tags dtype auto-detect (int64 vs int32) --------
    const int* tg32_all = (const int*)tags_raw;
    int det = 0;
#pragma unroll
    for (int i = 0; i < 64; i++) det |= tg32_all[2 * i + 1];
    const int tstride = (det == 0) ? 2 : 1;

    // ---------------- prologue: eT column j into registers (shared by chains) --
    unsigned long long col[NTAGS / 2];
#pragma unroll
    for (int k = 0; k < NTAGS / 2; k++) {
        float t0 = transitions[(size_t)(2 * k)     * NTAGS + j];
        float t1 = transitions[(size_t)(2 * k + 1) * NTAGS + j];
        col[k] = pk2(expf(t0), expf(t1));
    }

    // ---------------- gold score (both batches) ----------------
    const int*           tg0 = tg32_all + (size_t)b0 * SLEN * tstride;
    const int*           tg1 = tg32_all + (size_t)b1 * SLEN * tstride;
    const unsigned char* mk0 = mask + (size_t)b0 * SLEN;
    const unsigned char* mk1 = mask + (size_t)b1 * SLEN;
    const float*         em0 = emissions + (size_t)b0 * SLEN * NTAGS;
    const float*         em1 = emissions + (size_t)b1 * SLEN * NTAGS;

    float gold = 0.0f;
#pragma unroll
    for (int t = j; t < SLEN; t += NTAGS) {
        int   ta = tg0[t * tstride];
        int   tb = tg1[t * tstride];
        float ma = mk0[t] ? 1.0f : 0.0f;
        float mb = mk1[t] ? 1.0f : 0.0f;
        gold += ma * em0[(size_t)t * NTAGS + ta];
        gold += mb * em1[(size_t)t * NTAGS + tb];
        if (t + 1 < SLEN) {
            int   ta2 = tg0[(t + 1) * tstride];
            int   tb2 = tg1[(t + 1) * tstride];
            float ma2 = mk0[t + 1] ? 1.0f : 0.0f;
            float mb2 = mk1[t + 1] ? 1.0f : 0.0f;
            gold += ma2 * transitions[(size_t)ta * NTAGS + ta2];
            gold += mb2 * transitions[(size_t)tb * NTAGS + tb2];
        }
    }

    // ---------------- product-domain forward scan, two chains ----------------
    // invariant per chain: alpha(t) ~ C + log(u(t)) + e(t);
    // w(t) = u(t)*exp(e(t))/u0(t-1), stale-but-exact normalizer.
    float e0a = em0[j];
    float e0b = em1[j];
    if (j == 0) { u0s[0][0] = e0a; u0s[1][0] = e0b; }

    float ering0[4], ering1[4];
#pragma unroll
    for (int i = 0; i < 4; i++) {
        ering0[i] = em0[(size_t)(1 + i) * NTAGS + j];
        ering1[i] = em1[(size_t)(1 + i) * NTAGS + j];
    }
    __syncthreads();
    float c0a = u0s[0][0], c0b = u0s[1][0];
    double C0 = (double)c0a, C1 = (double)c0b;

    float w0 = __expf(e0a - c0a);
    float w1 = __expf(e0b - c0b);
    float up0 = 1.0f, up1 = 1.0f;         // u_prev
    float u0v = 1.0f, u1v = 1.0f;
    float E0 = 1.0f, E1 = 1.0f;

    for (int t = 1; t < SLEN; t++) {
        const int buf = t & 1;
        pbuf[0][buf][j] = w0;
        pbuf[1][buf][j] = w1;
        if (j == 0) { u0s[0][buf] = up0; u0s[1][buf] = up1; }
        float ec0 = ering0[(t - 1) & 3];
        float ec1 = ering1[(t - 1) & 3];
        if (t + 4 < SLEN) {
            ering0[(t - 1) & 3] = em0[(size_t)(t + 4) * NTAGS + j];
            ering1[(t - 1) & 3] = em1[(size_t)(t + 4) * NTAGS + j];
        }
        E0 = __expf(ec0);                 // off critical chain
        E1 = __expf(ec1);
        __syncthreads();                  // one barrier covers both chains
        float u0r0 = u0s[0][buf];
        float u0r1 = u0s[1][buf];
        float rcp0, rcp1;
        asm("rcp.approx.f32 %0,%1;" : "=f"(rcp0) : "f"(u0r0));
        asm("rcp.approx.f32 %0,%1;" : "=f"(rcp1) : "f"(u0r1));

        u0v = matvec128(pbuf[0][buf], col);   // chain-0 matvec
        u1v = matvec128(pbuf[1][buf], col);   // chain-1 fills chain-0's latency

        if (t < SLEN - 1) {
            C0 += (double)__logf(u0r0);
            C1 += (double)__logf(u0r1);
            w0  = u0v * (E0 * rcp0);      // ONE fmul on each chain
            w1  = u1v * (E1 * rcp1);
        }
        up0 = u0v;
        up1 = u1v;
    }

    // ---------------- epilogue: per-chain partition + gold, one barrier -------
    float z0 = u0v * E0;
    float z1 = u1v * E1;
#pragma unroll
    for (int o = 16; o > 0; o >>= 1) {
        z0   += __shfl_xor_sync(0xFFFFFFFFu, z0, o);
        z1   += __shfl_xor_sync(0xFFFFFFFFu, z1, o);
        gold += __shfl_xor_sync(0xFFFFFFFFu, gold, o);
    }
    if (lane == 0) {
        red[wid]     = z0;
        red[4 + wid] = z1;
        red[8 + wid] = gold;
    }
    __syncthreads();

    if (j == 0) {
        float sumz0   = (red[0] + red[1]) + (red[2]  + red[3]);
        float sumz1   = (red[4] + red[5]) + (red[6]  + red[7]);
        float goldtot = (red[8] + red[9]) + (red[10] + red[11]);
        double part = C0 + (double)__logf(sumz0) + C1 + (double)__logf(sumz1);
        atomicAdd(out, (float)part - goldtot);
    }
}

extern "C" void kernel_launch(void* const* d_in, const int* in_sizes, int n_in,
                              void* d_out, int out_size) {
    const float*         emissions   = (const float*)d_in[0];
    const void*          tags        = (const void*)d_in[1];
    const unsigned char* mask        = (const unsigned char*)d_in[2];
    const float*         transitions = (const float*)d_in[3];
    float*               out         = (float*)d_out;

    crf_zero_out<<<1, 1>>>(out);
    crf_forward_kernel<<<BATCH / 2, NTAGS>>>(emissions, tags, mask, transitions, out);
}

// round 14
// speedup vs baseline: 1.1747x; 1.1747x over previous
#include <cuda_runtime.h>
#include <cuda_bf16.h>
#include <cstdint>

#define NTAGS 128
#define BATCH 256
#define SLEN  512
#define NTHR  256              // thread (j,h): tag j = tid>>1, half h = tid&1
#define PBSTRIDE 136           // floats per w-buffer: 64 | 4 pad | 64 | 4 pad

// ---- packed f32x2 helpers (sm_103a) ----
__device__ __forceinline__ unsigned long long pk2(float x, float y) {
    unsigned long long r;
    asm("mov.b64 %0,{%1,%2};" : "=l"(r) : "f"(x), "f"(y));
    return r;
}
__device__ __forceinline__ void upk2(unsigned long long v, float& x, float& y) {
    asm("mov.b64 {%0,%1},%2;" : "=f"(x), "=f"(y) : "l"(v));
}
__device__ __forceinline__ unsigned long long ffma2(unsigned long long a,
                                                    unsigned long long b,
                                                    unsigned long long c) {
    unsigned long long d;
    asm("fma.rn.f32x2 %0,%1,%2,%3;" : "=l"(d) : "l"(a), "l"(b), "l"(c));
    return d;
}
__device__ __forceinline__ unsigned long long add2(unsigned long long a,
                                                   unsigned long long b) {
    unsigned long long d;
    asm("add.rn.f32x2 %0,%1,%2;" : "=l"(d) : "l"(a), "l"(b));
    return d;
}

__global__ void crf_zero_out(float* out) { out[0] = 0.0f; }

__global__ void __launch_bounds__(NTHR, 2)
crf_forward_kernel(const float* __restrict__ emissions,      // [B,S,NTAGS]
                   const void* __restrict__ tags_raw,        // [B,S] int32 OR int64
                   const unsigned char* __restrict__ mask,   // [B,S]
                   const float* __restrict__ transitions,    // [NTAGS,NTAGS]
                   float* __restrict__ out)                  // [1]
{
    const int b    = blockIdx.x;
    const int tid  = threadIdx.x;
    const int lane = tid & 31;
    const int wid  = tid >> 5;
    const int j    = tid >> 1;            // tag index (pair-shared)
    const int h    = tid & 1;             // half of the i-range

    __shared__ __align__(16) float pbuf[2][PBSTRIDE];   // double-buffered w
    __shared__ float u0s[2];
    __shared__ float red[24];

    // -------- tags dtype auto-detect (int64 vs int32) --------
    const int* tg32_all = (const int*)tags_raw;
    int det = 0;
#pragma unroll
    for (int i = 0; i < 64; i++) det |= tg32_all[2 * i + 1];
    const int tstride = (det == 0) ? 2 : 1;

    // -------- prologue: half-column of exp(T) into regs (64 regs) --------
    // col[k] = (exp T[64h+2k][j], exp T[64h+2k+1][j])
    unsigned long long col[32];
#pragma unroll
    for (int k = 0; k < 32; k++) {
        int i0 = h * 64 + 2 * k;
        float t0 = transitions[(size_t)i0       * NTAGS + j];
        float t1 = transitions[(size_t)(i0 + 1) * NTAGS + j];
        col[k] = pk2(expf(t0), expf(t1));
    }

    // -------- gold score (256 threads stride SLEN) --------
    const int*           tg = tg32_all + (size_t)b * SLEN * tstride;
    const unsigned char* mk = mask + (size_t)b * SLEN;
    const float*         em = emissions + (size_t)b * SLEN * NTAGS;

    float gold = 0.0f;
#pragma unroll
    for (int t = tid; t < SLEN; t += NTHR) {
        int   tt = tg[t * tstride];
        float m  = mk[t] ? 1.0f : 0.0f;
        gold += m * em[(size_t)t * NTAGS + tt];
        if (t + 1 < SLEN) {
            int   t2 = tg[(t + 1) * tstride];
            float m2 = mk[t + 1] ? 1.0f : 0.0f;
            gold += m2 * transitions[(size_t)tt * NTAGS + t2];
        }
    }

    // -------- product-domain forward scan --------
    // invariant: alpha_j(t) ~ C + log u_j(t) + e_j(t)
    // w_j(t) = u_j(t)*exp(e_j(t))/u0(t-1)  (1-step-stale normalizer; exact,
    //   since the u0 divided out of w is the same one whose log feeds C)
    float e0 = em[j];
    if (tid == 0) u0s[0] = e0;            // c0 = e_0(0)
    float ering[4];
#pragma unroll
    for (int i = 0; i < 4; i++)
        ering[i] = em[(size_t)(1 + i) * NTAGS + j];
    __syncthreads();
    float c0 = u0s[0];
    double C = (double)c0;

    float w      = __expf(e0 - c0);       // w(0), identical across the pair
    float u_prev = 1.0f;
    float u      = 1.0f;
    float E_cur  = 1.0f;

    // where this thread's half of w lives / where p_j is stored
    const char* pbase   = (const char*)pbuf + h * 272;        // 68 floats offset
    const int   my_slot = (j < 64) ? j : (68 + (j - 64));

    for (int t = 1; t < SLEN; t++) {
        const int buf = t & 1;
        if (h == 0) pbuf[buf][my_slot] = w;      // one writer per tag
        if (tid == 0) u0s[buf] = u_prev;
        float e_cur = ering[(t - 1) & 3];
        if (t + 4 < SLEN)
            ering[(t - 1) & 3] = em[(size_t)(t + 4) * NTAGS + j];
        E_cur = __expf(e_cur);                   // off critical chain
        __syncthreads();                         // single barrier per step
        float u0r = u0s[buf];
        float rcp;
        asm("rcp.approx.f32 %0,%1;" : "=f"(rcp) : "f"(u0r));

        // half matvec: 64 i's -> 16 LDS.128, 32 FFMA2, 4 u64 accumulators
        const ulonglong2* pq = (const ulonglong2*)(pbase + buf * (PBSTRIDE * 4));
        unsigned long long a0 = 0ull, a1 = 0ull, a2 = 0ull, a3 = 0ull;
#pragma unroll
        for (int k = 0; k < 16; k += 2) {
            ulonglong2 q0 = pq[k];
            ulonglong2 q1 = pq[k + 1];
            a0 = ffma2(q0.x, col[2 * k],     a0);
            a1 = ffma2(q0.y, col[2 * k + 1], a1);
            a2 = ffma2(q1.x, col[2 * k + 2], a2);
            a3 = ffma2(q1.y, col[2 * k + 3], a3);
        }
        unsigned long long st = add2(add2(a0, a1), add2(a2, a3));
        float sx, sy;
        upk2(st, sx, sy);
        float half_u = sx + sy;
        u = half_u + __shfl_xor_sync(0xFFFFFFFFu, half_u, 1);  // pair-reduce

        if (t < SLEN - 1) {
            C += (double)__logf(u0r);            // account applied scale
            w  = u * (E_cur * rcp);              // one fmul on the chain
        }
        u_prev = u;
    }

    // -------- epilogue: partition + gold, one barrier --------
    // each tag appears twice (h=0,1 identical) => halve the sum
    float z = u * E_cur;
#pragma unroll
    for (int o = 16; o > 0; o >>= 1) {
        z    += __shfl_xor_sync(0xFFFFFFFFu, z, o);
        gold += __shfl_xor_sync(0xFFFFFFFFu, gold, o);
    }
    if (lane == 0) {
        red[wid]     = z;
        red[8 + wid] = gold;
    }
    __syncthreads();

    if (tid == 0) {
        float sumz = 0.0f, goldtot = 0.0f;
#pragma unroll
        for (int i = 0; i < 8; i++) { sumz += red[i]; goldtot += red[8 + i]; }
        double part = C + (double)__logf(sumz * 0.5f);
        atomicAdd(out, (float)part - goldtot);
    }
}

extern "C" void kernel_launch(void* const* d_in, const int* in_sizes, int n_in,
                              void* d_out, int out_size) {
    const float*         emissions   = (const float*)d_in[0];
    const void*          tags        = (const void*)d_in[1];
    const unsigned char* mask        = (const unsigned char*)d_in[2];
    const float*         transitions = (const float*)d_in[3];
    float*               out         = (float*)d_out;

    crf_zero_out<<<1, 1>>>(out);
    crf_forward_kernel<<<BATCH, NTHR>>>(emissions, tags, mask, transitions, out);
}

// round 17
// speedup vs baseline: 1.6179x; 1.3773x over previous
#include <cuda_runtime.h>
#include <cuda_bf16.h>
#include <cstdint>

#define NTAGS 128
#define BATCH 256
#define SLEN  512

// ---- packed f32x2 helpers (sm_103a) ----
__device__ __forceinline__ unsigned long long pk2(float x, float y) {
    unsigned long long r;
    asm("mov.b64 %0,{%1,%2};" : "=l"(r) : "f"(x), "f"(y));
    return r;
}
__device__ __forceinline__ void upk2(unsigned long long v, float& x, float& y) {
    asm("mov.b64 {%0,%1},%2;" : "=f"(x), "=f"(y) : "l"(v));
}
__device__ __forceinline__ unsigned long long ffma2(unsigned long long a,
                                                    unsigned long long b,
                                                    unsigned long long c) {
    unsigned long long d;
    asm("fma.rn.f32x2 %0,%1,%2,%3;" : "=l"(d) : "l"(a), "l"(b), "l"(c));
    return d;
}
__device__ __forceinline__ unsigned long long add2(unsigned long long a,
                                                   unsigned long long b) {
    unsigned long long d;
    asm("add.rn.f32x2 %0,%1,%2;" : "=l"(d) : "l"(a), "l"(b));
    return d;
}

// Kahan compensated float add (replaces FP64 accumulation)
__device__ __forceinline__ void kadd(float& s, float& c, float x) {
    float y = x - c;
    float t = s + y;
    c = (t - s) - y;
    s = t;
}

// matvec: u_j = sum_i w_i * eT[i][j], w in smem (broadcast LDS.128), eT col in regs
__device__ __forceinline__ float matvec128(const float* __restrict__ pb,
                                           const unsigned long long* __restrict__ col) {
    const ulonglong2* pq = (const ulonglong2*)pb;
    unsigned long long a0 = 0ull, a1 = 0ull, a2 = 0ull, a3 = 0ull;
    unsigned long long a4 = 0ull, a5 = 0ull, a6 = 0ull, a7 = 0ull;
#pragma unroll
    for (int k = 0; k < 32; k += 4) {
        ulonglong2 q0 = pq[k];
        ulonglong2 q1 = pq[k + 1];
        ulonglong2 q2 = pq[k + 2];
        ulonglong2 q3 = pq[k + 3];
        a0 = ffma2(q0.x, col[2 * k],     a0);
        a1 = ffma2(q0.y, col[2 * k + 1], a1);
        a2 = ffma2(q1.x, col[2 * k + 2], a2);
        a3 = ffma2(q1.y, col[2 * k + 3], a3);
        a4 = ffma2(q2.x, col[2 * k + 4], a4);
        a5 = ffma2(q2.y, col[2 * k + 5], a5);
        a6 = ffma2(q3.x, col[2 * k + 6], a6);
        a7 = ffma2(q3.y, col[2 * k + 7], a7);
    }
    unsigned long long st = add2(add2(add2(a0, a1), add2(a2, a3)),
                                 add2(add2(a4, a5), add2(a6, a7)));
    float sx, sy;
    upk2(st, sx, sy);
    return sx + sy;
}

__global__ void crf_zero_out(float* out) { out[0] = 0.0f; }

__global__ void __launch_bounds__(NTAGS, 2)
crf_forward_kernel(const float* __restrict__ emissions,      // [B,S,NTAGS]
                   const void* __restrict__ tags_raw,        // [B,S] int32 OR int64
                   const unsigned char* __restrict__ mask,   // [B,S]
                   const float* __restrict__ transitions,    // [NTAGS,NTAGS]
                   float* __restrict__ out)                  // [1]
{
    const int b    = blockIdx.x;
    const int j    = threadIdx.x;         // tag owned by this thread
    const int lane = j & 31;
    const int wid  = j >> 5;

    __shared__ __align__(16) float pbuf[2][NTAGS];  // double-buffered w
    __shared__ float u0s[2];                        // double-buffered u0 broadcast
    __shared__ float red[8];

    // -------- tags dtype auto-detect (int64 vs int32) --------
    const int* tg32_all = (const int*)tags_raw;
    int det = 0;
#pragma unroll
    for (int i = 0; i < 64; i++) det |= tg32_all[2 * i + 1];
    const int tstride = (det == 0) ? 2 : 1;

    // ---------------- prologue: eT column j into registers ----------------
    unsigned long long col[NTAGS / 2];
#pragma unroll
    for (int k = 0; k < NTAGS / 2; k++) {
        float t0 = transitions[(size_t)(2 * k)     * NTAGS + j];
        float t1 = transitions[(size_t)(2 * k + 1) * NTAGS + j];
        col[k] = pk2(expf(t0), expf(t1));
    }

    // ---------------- gold score ----------------
    const int*           tg = tg32_all + (size_t)b * SLEN * tstride;
    const unsigned char* mk = mask + (size_t)b * SLEN;
    const float*         em = emissions + (size_t)b * SLEN * NTAGS;

    float gold = 0.0f;
#pragma unroll
    for (int t = j; t < SLEN; t += NTAGS) {
        int   tt = tg[t * tstride];
        float m  = mk[t] ? 1.0f : 0.0f;
        gold += m * em[(size_t)t * NTAGS + tt];
        if (t + 1 < SLEN) {
            int   t2 = tg[(t + 1) * tstride];
            float m2 = mk[t + 1] ? 1.0f : 0.0f;
            gold += m2 * transitions[(size_t)tt * NTAGS + t2];
        }
    }

    // ---------------- product-domain forward scan ----------------
    // invariant: alpha_j(t) ~ c0 + Ck + log u_j(t) + e_j(t)
    // w_j(t) = u_j(t)*exp(e_j(t))/u0(t-1), stale-but-exact normalizer.
    float e0 = em[j];
    if (j == 0) u0s[0] = e0;              // broadcast c0 = e_0(0)
    float ering[4];                       // STATIC indices only (unroll-4 below)
#pragma unroll
    for (int i = 0; i < 4; i++)
        ering[i] = em[(size_t)(1 + i) * NTAGS + j];
    __syncthreads();
    const float c0 = u0s[0];
    float Ck = 0.0f, Cc = 0.0f;           // Kahan float accumulator for sum(log u0)

    float w = __expf(e0 - c0);            // w(0)
    float u = 1.0f;                       // u(0) placeholder (log 1 = 0)
    float E = 1.0f;

    // one scan step; RS = compile-time ring slot, BUF = compile-time buffer,
    // DOPF = prefetch valid, DOUP = do C/w update (false only at t = SLEN-1)
#define SCAN_STEP(T, RS, BUF, DOPF, DOUP)                                   \
    {                                                                       \
        pbuf[BUF][j] = w;                                                   \
        if (j == 0) u0s[BUF] = u;          /* publish u0(t-1) */            \
        float e_cur = ering[RS];                                            \
        if (DOPF) ering[RS] = em[(size_t)((T) + 4) * NTAGS + j];            \
        E = __expf(e_cur);                 /* off critical chain */         \
        __syncthreads();                   /* single barrier per step */    \
        float u0r = u0s[BUF];                                               \
        float rcp;                                                          \
        asm("rcp.approx.f32 %0,%1;" : "=f"(rcp) : "f"(u0r));                \
        u = matvec128(pbuf[BUF], col);                                      \
        if (DOUP) {                                                         \
            kadd(Ck, Cc, __logf(u0r));     /* account applied scale */      \
            w = u * (E * rcp);             /* one fmul on the chain */      \
        }                                                                   \
    }

    // main loop: t = 1..508, four steps per iteration, all indices static.
    // tb = 1,5,...,505 (127 iterations). (tb-1) % 4 == 0 -> ring slot = s.
    for (int tb = 1; tb <= SLEN - 7; tb += 4) {
        SCAN_STEP(tb + 0, 0, 1, (tb + 0) + 4 < SLEN, true);
        SCAN_STEP(tb + 1, 1, 0, (tb + 1) + 4 < SLEN, true);
        SCAN_STEP(tb + 2, 2, 1, (tb + 2) + 4 < SLEN, true);
        SCAN_STEP(tb + 3, 3, 0, (tb + 3) + 4 < SLEN, true);
    }
    // tail: t = 509, 510 (full update), 511 (no update; E kept for epilogue)
    SCAN_STEP(509, 0, 1, false, true);
    SCAN_STEP(510, 1, 0, false, true);
    SCAN_STEP(511, 2, 1, false, false);
#undef SCAN_STEP

    // ---------------- epilogue: partition + gold, one barrier ----------------
    float z = u * E;                      // u_j(T) * exp(e_j(T)), all positive
#pragma unroll
    for (int o = 16; o > 0; o >>= 1) {
        z    += __shfl_xor_sync(0xFFFFFFFFu, z, o);
        gold += __shfl_xor_sync(0xFFFFFFFFu, gold, o);
    }
    if (lane == 0) {
        red[wid]     = z;
        red[4 + wid] = gold;
    }
    __syncthreads();

    if (j == 0) {
        float sumz    = (red[0] + red[1]) + (red[2] + red[3]);
        float goldtot = (red[4] + red[5]) + (red[6] + red[7]);
        double part = (double)c0 + (double)Ck + (double)Cc
                    + (double)__logf(sumz);
        atomicAdd(out, (float)part - goldtot);
    }
}

extern "C" void kernel_launch(void* const* d_in, const int* in_sizes, int n_in,
                              void* d_out, int out_size) {
    const float*         emissions   = (const float*)d_in[0];
    const void*          tags        = (const void*)d_in[1];
    const unsigned char* mask        = (const unsigned char*)d_in[2];
    const float*         transitions = (const float*)d_in[3];
    float*               out         = (float*)d_out;

    crf_zero_out<<<1, 1>>>(out);
    crf_forward_kernel<<<BATCH, NTAGS>>>(emissions, tags, mask, transitions, out);
}